// round 7
// baseline (speedup 1.0000x reference)
#include <cuda_runtime.h>
#include <math.h>

#define BB 8
#define NN 4096
#define DD 1024
#define HH 1792

#define GRID 296          // 148 SMs x 2 CTAs (forced by launch_bounds)
#define TPB 256
#define XBLKS 264         // phase-A blocks streaming x (33 per batch)
#define XPB 33            // x-blocks per batch
#define PFBLKS 32         // phase-A blocks prefetching weights
#define NCHU 256          // h-chunks in phase B
#define HPERU 7           // 256 * 7 = 1792
#define CGRP 8            // partials per phase-C block

// Scratch (allocation-free contract): __device__ globals.
__device__ float g_xbar[BB * DD];          // mean_n x  (atomic-accumulated)
__device__ float g_upart[NCHU][BB * DD];   // partial Wq^T @ kbar
__device__ float g_u[BB * DD];             // reduced u (atomic-accumulated)
__device__ float g_c[BB];                  // bq . kbar (atomic-accumulated)
__device__ float g_sink[PFBLKS];           // prefetch DCE sink
__device__ unsigned g_bar;                 // grid barrier counter

// ---------------------------------------------------------------------------
// K0: reset accumulators + barrier counter (runs before k_main each replay).
__global__ void k_zero() {
    int i = blockIdx.x * blockDim.x + threadIdx.x;
    if (i < BB * DD) { g_xbar[i] = 0.f; g_u[i] = 0.f; }
    if (i < BB) g_c[i] = 0.f;
    if (i == 0) g_bar = 0u;
}

// ---------------------------------------------------------------------------
// Software grid barrier. Safe: all GRID blocks co-resident (256 thr, 2/SM).
__device__ __forceinline__ void gridbar(unsigned target) {
    __syncthreads();
    if (threadIdx.x == 0) {
        __threadfence();
        atomicAdd(&g_bar, 1u);
        unsigned v;
        do {
            asm volatile("ld.volatile.global.u32 %0, [%1];"
                         : "=r"(v) : "l"(&g_bar));
            if (v < target) __nanosleep(64);
        } while (v < target);
        __threadfence();
    }
    __syncthreads();
}

// ---------------------------------------------------------------------------
__global__ void __launch_bounds__(TPB, 2)
k_main(const float* __restrict__ x,  const float* __restrict__ Wq,
       const float* __restrict__ bq, const float* __restrict__ Wk,
       const float* __restrict__ bk, float* __restrict__ out) {
    const int t = threadIdx.x;
    const int blk = blockIdx.x;
    const int warp = t >> 5, lane = t & 31;
    __shared__ float s_kb[HPERU][BB];

    // ===== Phase A: xbar (264 blocks) + weight L2-prefetch (32 blocks) ===
    if (blk < XBLKS) {
        const int b = blk / XPB;                   // 0..7
        const int c = blk % XPB;
        const int n0 = (c * NN) / XPB;
        const int n1 = ((c + 1) * NN) / XPB;
        const float4* xp = (const float4*)(x + (size_t)b * NN * DD);

        float4 acc = make_float4(0.f, 0.f, 0.f, 0.f);
        int n = n0;
        for (; n + 8 <= n1; n += 8) {
            #pragma unroll
            for (int j = 0; j < 8; j++) {
                float4 v = xp[(size_t)(n + j) * (DD / 4) + t];
                acc.x += v.x; acc.y += v.y; acc.z += v.z; acc.w += v.w;
            }
        }
        for (; n < n1; n++) {
            float4 v = xp[(size_t)n * (DD / 4) + t];
            acc.x += v.x; acc.y += v.y; acc.z += v.z; acc.w += v.w;
        }
        const float invN = 1.0f / (float)NN;
        float* dst = g_xbar + b * DD + t * 4;
        atomicAdd(dst + 0, acc.x * invN);
        atomicAdd(dst + 1, acc.y * invN);
        atomicAdd(dst + 2, acc.z * invN);
        atomicAdd(dst + 3, acc.w * invN);
    } else {
        // Prefetch Wk then Wq into L2 (read + fold into sink).
        const int p = blk - XBLKS;                 // 0..31
        const int nf4 = (HH * DD) / 4;             // float4s per weight matrix
        const int per = nf4 / PFBLKS;              // 114688/32 = 3584... (=nf4/32)
        const float4* wk4 = (const float4*)Wk;
        const float4* wq4 = (const float4*)Wq;
        float s = 0.f;
        const int base = p * per;
        for (int i = t; i < per; i += TPB) {
            float4 a = wk4[base + i];
            float4 b4 = wq4[base + i];
            s += a.x + a.w + b4.x + b4.w;
        }
        #pragma unroll
        for (int o = 16; o > 0; o >>= 1)
            s += __shfl_down_sync(0xffffffffu, s, o);
        if (lane == 0 && warp == 0) g_sink[p] = s;
    }
    gridbar(GRID);

    // ===== Phase B: kbar chunk (smem) + upart (weights now L2-hot) ======
    if (blk < NCHU) {
        const int hbase = blk * HPERU;
        if (warp < HPERU) {
            const int h = hbase + warp;
            const float4* wk = (const float4*)(Wk + (size_t)h * DD);
            float4 wreg[8];
            #pragma unroll
            for (int i = 0; i < 8; i++) wreg[i] = wk[i * 32 + lane];

            float acc[BB];
            #pragma unroll
            for (int b = 0; b < BB; b++) {
                const float4* xb = (const float4*)(g_xbar + b * DD);
                float s = 0.f;
                #pragma unroll
                for (int i = 0; i < 8; i++) {
                    float4 xv = xb[i * 32 + lane];
                    s += wreg[i].x * xv.x + wreg[i].y * xv.y
                       + wreg[i].z * xv.z + wreg[i].w * xv.w;
                }
                acc[b] = s;
            }
            #pragma unroll
            for (int b = 0; b < BB; b++)
                #pragma unroll
                for (int o = 16; o > 0; o >>= 1)
                    acc[b] += __shfl_xor_sync(0xffffffffu, acc[b], o);

            if (lane < BB) {
                const float kb = acc[lane] + bk[h];  // lane b = kbar[b][h]
                s_kb[warp][lane] = kb;
                atomicAdd(&g_c[lane], bq[h] * kb);
            }
        }
        __syncthreads();

        float4 acc[BB];
        #pragma unroll
        for (int b = 0; b < BB; b++) acc[b] = make_float4(0.f, 0.f, 0.f, 0.f);
        #pragma unroll
        for (int hh = 0; hh < HPERU; hh++) {
            const float4 w = ((const float4*)(Wq + (size_t)(hbase + hh) * DD))[t];
            #pragma unroll
            for (int b = 0; b < BB; b++) {
                const float kb = s_kb[hh][b];
                acc[b].x = fmaf(w.x, kb, acc[b].x);
                acc[b].y = fmaf(w.y, kb, acc[b].y);
                acc[b].z = fmaf(w.z, kb, acc[b].z);
                acc[b].w = fmaf(w.w, kb, acc[b].w);
            }
        }
        float4* dst = (float4*)(g_upart[blk]);
        #pragma unroll
        for (int b = 0; b < BB; b++) dst[b * (DD / 4) + t] = acc[b];
    }
    gridbar(2u * GRID);

    // ===== Phase C: u = sum_c upart[c]  (L2-hot) =========================
    if (blk < NCHU) {                       // 256 blocks: 8 strips x 32 groups
        const int ib = blk & 7;
        const int cbase = (blk >> 3) * CGRP;
        const int f4 = ib * 256 + t;
        float4 s = make_float4(0.f, 0.f, 0.f, 0.f);
        #pragma unroll
        for (int j = 0; j < CGRP; j++) {
            float4 v = ((const float4*)(g_upart[cbase + j]))[f4];
            s.x += v.x; s.y += v.y; s.z += v.z; s.w += v.w;
        }
        float* dst = g_u + f4 * 4;
        atomicAdd(dst + 0, s.x);
        atomicAdd(dst + 1, s.y);
        atomicAdd(dst + 2, s.z);
        atomicAdd(dst + 3, s.w);
    }
    gridbar(3u * GRID);

    // ===== Phase D: scores, REVERSE order (harvest L2-resident x tail) ==
    {
        const float scale = rsqrtf((float)HH);
        const int wglobal = blk * 8 + warp;          // 0..2367
        for (int rr = wglobal; rr < BB * NN; rr += GRID * 8) {
            const int r = (BB * NN - 1) - rr;        // reverse traversal
            const int b = r >> 12;                   // N = 4096
            const float4* xp = (const float4*)(x + (size_t)r * DD);
            const float4* up = (const float4*)(g_u + b * DD);
            float acc = 0.f;
            #pragma unroll
            for (int i = 0; i < 8; i++) {
                float4 xv = xp[i * 32 + lane];
                float4 uv = up[i * 32 + lane];
                acc += xv.x * uv.x + xv.y * uv.y + xv.z * uv.z + xv.w * uv.w;
            }
            #pragma unroll
            for (int o = 16; o > 0; o >>= 1)
                acc += __shfl_down_sync(0xffffffffu, acc, o);
            if (lane == 0) out[r] = scale * (acc + g_c[b]);
        }
    }
}

// ---------------------------------------------------------------------------
extern "C" void kernel_launch(void* const* d_in, const int* in_sizes, int n_in,
                              void* d_out, int out_size) {
    const float* x  = (const float*)d_in[0];   // [B, N, D] f32
    const float* Wq = (const float*)d_in[1];   // [H, D]    f32
    const float* bq = (const float*)d_in[2];   // [H]       f32
    const float* Wk = (const float*)d_in[3];   // [H, D]    f32
    const float* bk = (const float*)d_in[4];   // [H]       f32
    float* out = (float*)d_out;                // [B, N]    f32

    k_zero<<<(BB * DD + TPB - 1) / TPB, TPB>>>();
    k_main<<<GRID, TPB>>>(x, Wq, bq, Wk, bk, out);
}